// round 11
// baseline (speedup 1.0000x reference)
#include <cuda_runtime.h>
#include <cstdint>

// ---------------------------------------------------------------------------
// SESConv_H_H — TF32 mma.sync implicit conv.
// R10: 4 output rows per warp — each B fragment feeds up to 4 mmas
// (wf/mma 1.7 -> 1.05). Tile 32x32, 2 CTAs/SM. Same math/order as R9.
// ---------------------------------------------------------------------------

#define SG    12
#define CIN   16
#define COUT  16
#define BATCH 8
#define HWD   128

#define TILE_W 32
#define TILE_H 32
#define HALO_W 36
#define HALO_H 36
#define NPIX   (HALO_W * HALO_H)   // 1296
#define SEC    (NPIX * 8 + 16)     // 10384 uints per ch-section
#define XS_UINTS (2 * SEC)         // 20768
#define KS_UINTS 6400              // 25 taps * 2 chunks * 128
#define SMEM_BYTES ((XS_UINTS + KS_UINTS) * 4)   // 108672 B

// Keff (tf32 bits): [g][ij][(tap*2+ch)*128 + lane*4 + j]
// j -> (o = grp + 8*(j&1), c = ch*8 + tig + 4*(j>>1)), lane = grp*4+tig
__device__ uint32_t g_keff[SG * 4 * 50 * 128];

__device__ __forceinline__ uint32_t tf32r(float v) {
    uint32_t r;
    asm("cvt.rna.tf32.f32 %0, %1;" : "=r"(r) : "f"(v));
    return r;
}

__device__ __forceinline__ void mma_tf32(float* d, uint4 A, uint2 B) {
    asm volatile(
        "mma.sync.aligned.m16n8k8.row.col.f32.tf32.tf32.f32 "
        "{%0,%1,%2,%3}, {%4,%5,%6,%7}, {%8,%9}, {%0,%1,%2,%3};"
        : "+f"(d[0]), "+f"(d[1]), "+f"(d[2]), "+f"(d[3])
        : "r"(A.x), "r"(A.y), "r"(A.z), "r"(A.w), "r"(B.x), "r"(B.y));
}

__global__ void build_keff_kernel(const float* __restrict__ weight,
                                  const float* __restrict__ basis) {
    const int total = SG * 4 * 50 * 128;
    int idx = blockIdx.x * blockDim.x + threadIdx.x;
    if (idx >= total) return;
    const int within = idx % 6400;
    const int gij    = idx / 6400;
    const int g  = gij / 4;
    const int ij = gij % 4;
    const int blk = within / 128;     // tap*2 + ch
    const int r   = within % 128;
    const int tap = blk >> 1;
    const int ch  = blk & 1;
    const int lane = r >> 2;
    const int j    = r & 3;
    const int grp  = lane >> 2;
    const int tig  = lane & 3;
    const int o = grp + 8 * (j & 1);
    const int c = ch * 8 + tig + 4 * (j >> 1);
    float v = 0.f;
#pragma unroll
    for (int f = 0; f < 9; ++f)
        v += weight[((o * CIN + c) * 4 + ij) * 9 + f] *
             basis[(f * SG + g) * 25 + tap];
    g_keff[idx] = tf32r(v);
}

__global__ void __launch_bounds__(256, 2)
ses_mma_kernel(const float* __restrict__ x, float* __restrict__ out) {
    extern __shared__ uint32_t dyn[];
    uint32_t* xs = dyn;                 // 2 ch-sections: [pix][tig*2+h]
    uint32_t* ks = dyn + XS_UINTS;      // Keff stage

    const int tid  = threadIdx.x;
    const int w    = tid >> 5;          // warp -> output rows 4w..4w+3
    const int lane = tid & 31;
    const int grp  = lane >> 2;
    const int tig  = lane & 3;

    const int bz = blockIdx.z;
    const int b  = bz / SG;
    const int g  = bz % SG;
    const int nr = g / 3;
    const int ns = g % 3;
    const int tx0 = blockIdx.x * TILE_W;
    const int ty0 = blockIdx.y * TILE_H;

    int ijv[4];
    int nv = 0;
#pragma unroll
    for (int ij = 0; ij < 4; ++ij)
        if (ns + (ij & 1) < 3) ijv[nv++] = ij;

    float acc[4][4][4];
#pragma unroll
    for (int r = 0; r < 4; ++r)
#pragma unroll
        for (int cr = 0; cr < 4; ++cr)
#pragma unroll
            for (int q = 0; q < 4; ++q) acc[r][cr][q] = 0.f;

    for (int sIdx = 0; sIdx < nv; ++sIdx) {
        const int ij = ijv[sIdx];
        const int sp = ((nr + (ij >> 1)) & 3) * 3 + (ns + (ij & 1));
        const float* xb =
            x + ((((size_t)b * CIN) * SG + sp) << 14);   // + c*(SG<<14)

        // fill: one uint2 (c, c+4) per element-pair. 2*4*NPIX pairs.
        for (int e = tid; e < 2 * 4 * NPIX; e += 256) {
            const int tg  = e & 3;
            const int pe  = e >> 2;
            const int ch  = pe / NPIX;
            const int pix = pe - ch * NPIX;
            const int rr  = pix / HALO_W;
            const int cc  = pix - rr * HALO_W;
            const int gy = ty0 + rr - 2;
            const int gx = tx0 + cc - 2;
            const int c0 = ch * 8 + tg;
            uint2 val = make_uint2(0u, 0u);
            if ((unsigned)gy < (unsigned)HWD && (unsigned)gx < (unsigned)HWD) {
                const size_t off = (size_t)gy * HWD + gx;
                const size_t pstride = (size_t)SG << 14;
                val.x = tf32r(__ldg(xb + (size_t)c0 * pstride + off));
                val.y = tf32r(__ldg(xb + (size_t)(c0 + 4) * pstride + off));
            }
            *reinterpret_cast<uint2*>(xs + ch * SEC + pix * 8 + tg * 2) = val;
        }
        // fill Keff stage (uint4 copies, conflict-free)
        const uint4* kp =
            reinterpret_cast<const uint4*>(g_keff + (size_t)(g * 4 + ij) * 6400);
        uint4* kd = reinterpret_cast<uint4*>(ks);
        for (int e = tid; e < KS_UINTS / 4; e += 256) kd[e] = kp[e];
        __syncthreads();

#pragma unroll
        for (int ch = 0; ch < 2; ++ch) {
            const uint32_t* kbase = ks + ch * 128 + lane * 4;
            const uint32_t* xsec =
                xs + ch * SEC + (4 * w * HALO_W + grp) * 8 + tig * 2;

#pragma unroll
            for (int kx = 0; kx < 5; ++kx) {
                uint4 A[5];
#pragma unroll
                for (int ky = 0; ky < 5; ++ky)
                    A[ky] = *reinterpret_cast<const uint4*>(
                        kbase + (ky * 5 + kx) * 256);

                const uint32_t* pb = xsec + kx * 8;
#pragma unroll
                for (int u = 0; u < 8; ++u) {
                    const uint32_t* pu = pb + u * (HALO_W * 8);
                    uint2 Bv[4];
#pragma unroll
                    for (int cr = 0; cr < 4; ++cr)
                        Bv[cr] = *reinterpret_cast<const uint2*>(pu + cr * 64);
#pragma unroll
                    for (int ky = 0; ky < 5; ++ky) {
                        if (ky <= u && u - ky <= 3) {
                            const int r = u - ky;
#pragma unroll
                            for (int cr = 0; cr < 4; ++cr)
                                mma_tf32(acc[r][cr], A[ky], Bv[cr]);
                        }
                    }
                }
            }
        }
        __syncthreads();
    }

#pragma unroll
    for (int r = 0; r < 4; ++r) {
        const int row = ty0 + 4 * w + r;
#pragma unroll
        for (int cr = 0; cr < 4; ++cr) {
            const int px = tx0 + cr * 8 + tig * 2;
            float* o0 = out + ((((size_t)b * COUT + grp)     * SG + g) << 14) +
                        row * HWD + px;
            float* o1 = out + ((((size_t)b * COUT + grp + 8) * SG + g) << 14) +
                        row * HWD + px;
            *reinterpret_cast<float2*>(o0) =
                make_float2(acc[r][cr][0], acc[r][cr][1]);
            *reinterpret_cast<float2*>(o1) =
                make_float2(acc[r][cr][2], acc[r][cr][3]);
        }
    }
}

extern "C" void kernel_launch(void* const* d_in, const int* in_sizes, int n_in,
                              void* d_out, int out_size) {
    const float* x      = (const float*)d_in[0];
    const float* weight = (const float*)d_in[1];
    const float* basis  = (const float*)d_in[2];
    float* out = (float*)d_out;

    const int total = SG * 4 * 50 * 128;
    build_keff_kernel<<<(total + 255) / 256, 256>>>(weight, basis);

    cudaFuncSetAttribute(ses_mma_kernel,
                         cudaFuncAttributeMaxDynamicSharedMemorySize,
                         SMEM_BYTES);
    dim3 grid(HWD / TILE_W, HWD / TILE_H, BATCH * SG);
    ses_mma_kernel<<<grid, 256, SMEM_BYTES>>>(x, out);
}

// round 12
// speedup vs baseline: 1.0609x; 1.0609x over previous
#include <cuda_runtime.h>
#include <cstdint>

// ---------------------------------------------------------------------------
// SESConv_H_H — TF32 mma.sync implicit conv.
// R11: 4-row B-reuse (from R10) at 3 CTAs/SM (from R9): tile 16x32,
// warp = 4 rows x 2 cr-tiles, 32 acc regs. Same math/order as R9/R10.
// ---------------------------------------------------------------------------

#define SG    12
#define CIN   16
#define COUT  16
#define BATCH 8
#define HWD   128

#define TILE_W 16
#define TILE_H 32
#define HALO_W 20
#define HALO_H 36
#define NPIX   (HALO_W * HALO_H)   // 720
#define SEC    (NPIX * 8 + 16)     // 5776 uints per ch-section
#define XS_UINTS (2 * SEC)         // 11552
#define KS_UINTS 6400              // 25 taps * 2 chunks * 128
#define SMEM_BYTES ((XS_UINTS + KS_UINTS) * 4)   // 71808 B

// Keff (tf32 bits): [g][ij][(tap*2+ch)*128 + lane*4 + j]
// j -> (o = grp + 8*(j&1), c = ch*8 + tig + 4*(j>>1)), lane = grp*4+tig
__device__ uint32_t g_keff[SG * 4 * 50 * 128];

__device__ __forceinline__ uint32_t tf32r(float v) {
    uint32_t r;
    asm("cvt.rna.tf32.f32 %0, %1;" : "=r"(r) : "f"(v));
    return r;
}

__device__ __forceinline__ void mma_tf32(float* d, uint4 A, uint2 B) {
    asm volatile(
        "mma.sync.aligned.m16n8k8.row.col.f32.tf32.tf32.f32 "
        "{%0,%1,%2,%3}, {%4,%5,%6,%7}, {%8,%9}, {%0,%1,%2,%3};"
        : "+f"(d[0]), "+f"(d[1]), "+f"(d[2]), "+f"(d[3])
        : "r"(A.x), "r"(A.y), "r"(A.z), "r"(A.w), "r"(B.x), "r"(B.y));
}

__global__ void build_keff_kernel(const float* __restrict__ weight,
                                  const float* __restrict__ basis) {
    const int total = SG * 4 * 50 * 128;
    int idx = blockIdx.x * blockDim.x + threadIdx.x;
    if (idx >= total) return;
    const int within = idx % 6400;
    const int gij    = idx / 6400;
    const int g  = gij / 4;
    const int ij = gij % 4;
    const int blk = within / 128;     // tap*2 + ch
    const int r   = within % 128;
    const int tap = blk >> 1;
    const int ch  = blk & 1;
    const int lane = r >> 2;
    const int j    = r & 3;
    const int grp  = lane >> 2;
    const int tig  = lane & 3;
    const int o = grp + 8 * (j & 1);
    const int c = ch * 8 + tig + 4 * (j >> 1);
    float v = 0.f;
#pragma unroll
    for (int f = 0; f < 9; ++f)
        v += weight[((o * CIN + c) * 4 + ij) * 9 + f] *
             basis[(f * SG + g) * 25 + tap];
    g_keff[idx] = tf32r(v);
}

__global__ void __launch_bounds__(256, 3)
ses_mma_kernel(const float* __restrict__ x, float* __restrict__ out) {
    extern __shared__ uint32_t dyn[];
    uint32_t* xs = dyn;                 // 2 ch-sections: [pix][tig*2+h]
    uint32_t* ks = dyn + XS_UINTS;      // Keff stage

    const int tid  = threadIdx.x;
    const int w    = tid >> 5;          // warp -> output rows 4w..4w+3
    const int lane = tid & 31;
    const int grp  = lane >> 2;
    const int tig  = lane & 3;

    const int bz = blockIdx.z;
    const int b  = bz / SG;
    const int g  = bz % SG;
    const int nr = g / 3;
    const int ns = g % 3;
    const int tx0 = blockIdx.x * TILE_W;
    const int ty0 = blockIdx.y * TILE_H;

    int ijv[4];
    int nv = 0;
#pragma unroll
    for (int ij = 0; ij < 4; ++ij)
        if (ns + (ij & 1) < 3) ijv[nv++] = ij;

    float acc[4][2][4];
#pragma unroll
    for (int r = 0; r < 4; ++r)
#pragma unroll
        for (int cr = 0; cr < 2; ++cr)
#pragma unroll
            for (int q = 0; q < 4; ++q) acc[r][cr][q] = 0.f;

    for (int sIdx = 0; sIdx < nv; ++sIdx) {
        const int ij = ijv[sIdx];
        const int sp = ((nr + (ij >> 1)) & 3) * 3 + (ns + (ij & 1));
        const float* xb =
            x + ((((size_t)b * CIN) * SG + sp) << 14);   // + c*(SG<<14)

        // fill: one uint2 (c, c+4) per element-pair. 2*4*NPIX pairs.
        for (int e = tid; e < 2 * 4 * NPIX; e += 256) {
            const int tg  = e & 3;
            const int pe  = e >> 2;
            const int ch  = pe / NPIX;
            const int pix = pe - ch * NPIX;
            const int rr  = pix / HALO_W;
            const int cc  = pix - rr * HALO_W;
            const int gy = ty0 + rr - 2;
            const int gx = tx0 + cc - 2;
            const int c0 = ch * 8 + tg;
            uint2 val = make_uint2(0u, 0u);
            if ((unsigned)gy < (unsigned)HWD && (unsigned)gx < (unsigned)HWD) {
                const size_t off = (size_t)gy * HWD + gx;
                const size_t pstride = (size_t)SG << 14;
                val.x = tf32r(__ldg(xb + (size_t)c0 * pstride + off));
                val.y = tf32r(__ldg(xb + (size_t)(c0 + 4) * pstride + off));
            }
            *reinterpret_cast<uint2*>(xs + ch * SEC + pix * 8 + tg * 2) = val;
        }
        // fill Keff stage (uint4 copies, conflict-free)
        const uint4* kp =
            reinterpret_cast<const uint4*>(g_keff + (size_t)(g * 4 + ij) * 6400);
        uint4* kd = reinterpret_cast<uint4*>(ks);
        for (int e = tid; e < KS_UINTS / 4; e += 256) kd[e] = kp[e];
        __syncthreads();

#pragma unroll
        for (int ch = 0; ch < 2; ++ch) {
            const uint32_t* kbase = ks + ch * 128 + lane * 4;
            const uint32_t* xsec =
                xs + ch * SEC + (4 * w * HALO_W + grp) * 8 + tig * 2;

#pragma unroll
            for (int kx = 0; kx < 5; ++kx) {
                uint4 A[5];
#pragma unroll
                for (int ky = 0; ky < 5; ++ky)
                    A[ky] = *reinterpret_cast<const uint4*>(
                        kbase + (ky * 5 + kx) * 256);

                const uint32_t* pb = xsec + kx * 8;
#pragma unroll
                for (int u = 0; u < 8; ++u) {
                    const uint32_t* pu = pb + u * (HALO_W * 8);
                    uint2 Bv[2];
#pragma unroll
                    for (int cr = 0; cr < 2; ++cr)
                        Bv[cr] = *reinterpret_cast<const uint2*>(pu + cr * 64);
#pragma unroll
                    for (int ky = 0; ky < 5; ++ky) {
                        if (ky <= u && u - ky <= 3) {
                            const int r = u - ky;
#pragma unroll
                            for (int cr = 0; cr < 2; ++cr)
                                mma_tf32(acc[r][cr], A[ky], Bv[cr]);
                        }
                    }
                }
            }
        }
        __syncthreads();
    }

#pragma unroll
    for (int r = 0; r < 4; ++r) {
        const int row = ty0 + 4 * w + r;
#pragma unroll
        for (int cr = 0; cr < 2; ++cr) {
            const int px = tx0 + cr * 8 + tig * 2;
            float* o0 = out + ((((size_t)b * COUT + grp)     * SG + g) << 14) +
                        row * HWD + px;
            float* o1 = out + ((((size_t)b * COUT + grp + 8) * SG + g) << 14) +
                        row * HWD + px;
            *reinterpret_cast<float2*>(o0) =
                make_float2(acc[r][cr][0], acc[r][cr][1]);
            *reinterpret_cast<float2*>(o1) =
                make_float2(acc[r][cr][2], acc[r][cr][3]);
        }
    }
}

extern "C" void kernel_launch(void* const* d_in, const int* in_sizes, int n_in,
                              void* d_out, int out_size) {
    const float* x      = (const float*)d_in[0];
    const float* weight = (const float*)d_in[1];
    const float* basis  = (const float*)d_in[2];
    float* out = (float*)d_out;

    const int total = SG * 4 * 50 * 128;
    build_keff_kernel<<<(total + 255) / 256, 256>>>(weight, basis);

    cudaFuncSetAttribute(ses_mma_kernel,
                         cudaFuncAttributeMaxDynamicSharedMemorySize,
                         SMEM_BYTES);
    dim3 grid(HWD / TILE_W, HWD / TILE_H, BATCH * SG);
    ses_mma_kernel<<<grid, 256, SMEM_BYTES>>>(x, out);
}

// round 13
// speedup vs baseline: 1.1614x; 1.0947x over previous
#include <cuda_runtime.h>
#include <cstdint>

// ---------------------------------------------------------------------------
// SESConv_H_H — TF32 mma.sync implicit conv.
// R12: A fragments via LDG from L1/L2 (Keff is hot: 25.6KB shared by 256
// CTAs) — removes the ks smem stage and 38% of crossbar traffic.
// Tiling/compute from R11. Same math/order: rel_err must stay 2.930714e-4.
// ---------------------------------------------------------------------------

#define SG    12
#define CIN   16
#define COUT  16
#define BATCH 8
#define HWD   128

#define TILE_W 16
#define TILE_H 32
#define HALO_W 20
#define HALO_H 36
#define NPIX   (HALO_W * HALO_H)   // 720
#define SEC    (NPIX * 8 + 16)     // 5776 uints per ch-section
#define XS_UINTS (2 * SEC)         // 11552
#define SMEM_BYTES (XS_UINTS * 4)  // 46208 B

// Keff (tf32 bits): [g][ij][(tap*2+ch)*128 + lane*4 + j]
// j -> (o = grp + 8*(j&1), c = ch*8 + tig + 4*(j>>1)), lane = grp*4+tig
__device__ uint32_t g_keff[SG * 4 * 50 * 128];

__device__ __forceinline__ uint32_t tf32r(float v) {
    uint32_t r;
    asm("cvt.rna.tf32.f32 %0, %1;" : "=r"(r) : "f"(v));
    return r;
}

__device__ __forceinline__ void mma_tf32(float* d, uint4 A, uint2 B) {
    asm volatile(
        "mma.sync.aligned.m16n8k8.row.col.f32.tf32.tf32.f32 "
        "{%0,%1,%2,%3}, {%4,%5,%6,%7}, {%8,%9}, {%0,%1,%2,%3};"
        : "+f"(d[0]), "+f"(d[1]), "+f"(d[2]), "+f"(d[3])
        : "r"(A.x), "r"(A.y), "r"(A.z), "r"(A.w), "r"(B.x), "r"(B.y));
}

__global__ void build_keff_kernel(const float* __restrict__ weight,
                                  const float* __restrict__ basis) {
    const int total = SG * 4 * 50 * 128;
    int idx = blockIdx.x * blockDim.x + threadIdx.x;
    if (idx >= total) return;
    const int within = idx % 6400;
    const int gij    = idx / 6400;
    const int g  = gij / 4;
    const int ij = gij % 4;
    const int blk = within / 128;     // tap*2 + ch
    const int r   = within % 128;
    const int tap = blk >> 1;
    const int ch  = blk & 1;
    const int lane = r >> 2;
    const int j    = r & 3;
    const int grp  = lane >> 2;
    const int tig  = lane & 3;
    const int o = grp + 8 * (j & 1);
    const int c = ch * 8 + tig + 4 * (j >> 1);
    float v = 0.f;
#pragma unroll
    for (int f = 0; f < 9; ++f)
        v += weight[((o * CIN + c) * 4 + ij) * 9 + f] *
             basis[(f * SG + g) * 25 + tap];
    g_keff[idx] = tf32r(v);
}

__global__ void __launch_bounds__(256, 3)
ses_mma_kernel(const float* __restrict__ x, float* __restrict__ out) {
    extern __shared__ uint32_t dyn[];
    uint32_t* xs = dyn;                 // 2 ch-sections: [pix][tig*2+h]

    const int tid  = threadIdx.x;
    const int w    = tid >> 5;          // warp -> output rows 4w..4w+3
    const int lane = tid & 31;
    const int grp  = lane >> 2;
    const int tig  = lane & 3;

    const int bz = blockIdx.z;
    const int b  = bz / SG;
    const int g  = bz % SG;
    const int nr = g / 3;
    const int ns = g % 3;
    const int tx0 = blockIdx.x * TILE_W;
    const int ty0 = blockIdx.y * TILE_H;

    int ijv[4];
    int nv = 0;
#pragma unroll
    for (int ij = 0; ij < 4; ++ij)
        if (ns + (ij & 1) < 3) ijv[nv++] = ij;

    float acc[4][2][4];
#pragma unroll
    for (int r = 0; r < 4; ++r)
#pragma unroll
        for (int cr = 0; cr < 2; ++cr)
#pragma unroll
            for (int q = 0; q < 4; ++q) acc[r][cr][q] = 0.f;

    for (int sIdx = 0; sIdx < nv; ++sIdx) {
        const int ij = ijv[sIdx];
        const int sp = ((nr + (ij >> 1)) & 3) * 3 + (ns + (ij & 1));
        const float* xb =
            x + ((((size_t)b * CIN) * SG + sp) << 14);   // + c*(SG<<14)

        // fill: one uint2 (c, c+4) per element-pair. 2*4*NPIX pairs.
        for (int e = tid; e < 2 * 4 * NPIX; e += 256) {
            const int tg  = e & 3;
            const int pe  = e >> 2;
            const int ch  = pe / NPIX;
            const int pix = pe - ch * NPIX;
            const int rr  = pix / HALO_W;
            const int cc  = pix - rr * HALO_W;
            const int gy = ty0 + rr - 2;
            const int gx = tx0 + cc - 2;
            const int c0 = ch * 8 + tg;
            uint2 val = make_uint2(0u, 0u);
            if ((unsigned)gy < (unsigned)HWD && (unsigned)gx < (unsigned)HWD) {
                const size_t off = (size_t)gy * HWD + gx;
                const size_t pstride = (size_t)SG << 14;
                val.x = tf32r(__ldg(xb + (size_t)c0 * pstride + off));
                val.y = tf32r(__ldg(xb + (size_t)(c0 + 4) * pstride + off));
            }
            *reinterpret_cast<uint2*>(xs + ch * SEC + pix * 8 + tg * 2) = val;
        }
        __syncthreads();

        // A fragments straight from global (L1/L2-resident, coalesced)
        const uint32_t* kg = g_keff + (size_t)(g * 4 + ij) * 6400 + lane * 4;

#pragma unroll
        for (int ch = 0; ch < 2; ++ch) {
            const uint32_t* kbase = kg + ch * 128;
            const uint32_t* xsec =
                xs + ch * SEC + (4 * w * HALO_W + grp) * 8 + tig * 2;

#pragma unroll
            for (int kx = 0; kx < 5; ++kx) {
                uint4 A[5];
#pragma unroll
                for (int ky = 0; ky < 5; ++ky)
                    A[ky] = __ldg(reinterpret_cast<const uint4*>(
                        kbase + (ky * 5 + kx) * 256));

                const uint32_t* pb = xsec + kx * 8;
#pragma unroll
                for (int u = 0; u < 8; ++u) {
                    const uint32_t* pu = pb + u * (HALO_W * 8);
                    uint2 Bv[2];
#pragma unroll
                    for (int cr = 0; cr < 2; ++cr)
                        Bv[cr] = *reinterpret_cast<const uint2*>(pu + cr * 64);
#pragma unroll
                    for (int ky = 0; ky < 5; ++ky) {
                        if (ky <= u && u - ky <= 3) {
                            const int r = u - ky;
#pragma unroll
                            for (int cr = 0; cr < 2; ++cr)
                                mma_tf32(acc[r][cr], A[ky], Bv[cr]);
                        }
                    }
                }
            }
        }
        __syncthreads();
    }

#pragma unroll
    for (int r = 0; r < 4; ++r) {
        const int row = ty0 + 4 * w + r;
#pragma unroll
        for (int cr = 0; cr < 2; ++cr) {
            const int px = tx0 + cr * 8 + tig * 2;
            float* o0 = out + ((((size_t)b * COUT + grp)     * SG + g) << 14) +
                        row * HWD + px;
            float* o1 = out + ((((size_t)b * COUT + grp + 8) * SG + g) << 14) +
                        row * HWD + px;
            *reinterpret_cast<float2*>(o0) =
                make_float2(acc[r][cr][0], acc[r][cr][1]);
            *reinterpret_cast<float2*>(o1) =
                make_float2(acc[r][cr][2], acc[r][cr][3]);
        }
    }
}

extern "C" void kernel_launch(void* const* d_in, const int* in_sizes, int n_in,
                              void* d_out, int out_size) {
    const float* x      = (const float*)d_in[0];
    const float* weight = (const float*)d_in[1];
    const float* basis  = (const float*)d_in[2];
    float* out = (float*)d_out;

    const int total = SG * 4 * 50 * 128;
    build_keff_kernel<<<(total + 255) / 256, 256>>>(weight, basis);

    cudaFuncSetAttribute(ses_mma_kernel,
                         cudaFuncAttributeMaxDynamicSharedMemorySize,
                         SMEM_BYTES);
    dim3 grid(HWD / TILE_W, HWD / TILE_H, BATCH * SG);
    ses_mma_kernel<<<grid, 256, SMEM_BYTES>>>(x, out);
}

// round 14
// speedup vs baseline: 1.2680x; 1.0918x over previous
#include <cuda_runtime.h>
#include <cstdint>

// ---------------------------------------------------------------------------
// SESConv_H_H — TF32 mma.sync implicit conv.
// R13: x fed as raw fp32 bits (HMMA.TF32 truncates; no cvt in fill),
// interior-block fast path. Structure otherwise identical to R12.
// ---------------------------------------------------------------------------

#define SG    12
#define CIN   16
#define COUT  16
#define BATCH 8
#define HWD   128

#define TILE_W 16
#define TILE_H 32
#define HALO_W 20
#define HALO_H 36
#define NPIX   (HALO_W * HALO_H)   // 720
#define SEC    (NPIX * 8 + 16)     // 5776 uints per ch-section
#define XS_UINTS (2 * SEC)         // 11552
#define SMEM_BYTES (XS_UINTS * 4)  // 46208 B

// Keff (tf32 bits): [g][ij][(tap*2+ch)*128 + lane*4 + j]
// j -> (o = grp + 8*(j&1), c = ch*8 + tig + 4*(j>>1)), lane = grp*4+tig
__device__ uint32_t g_keff[SG * 4 * 50 * 128];

__device__ __forceinline__ uint32_t tf32r(float v) {
    uint32_t r;
    asm("cvt.rna.tf32.f32 %0, %1;" : "=r"(r) : "f"(v));
    return r;
}

__device__ __forceinline__ void mma_tf32(float* d, uint4 A, uint2 B) {
    asm volatile(
        "mma.sync.aligned.m16n8k8.row.col.f32.tf32.tf32.f32 "
        "{%0,%1,%2,%3}, {%4,%5,%6,%7}, {%8,%9}, {%0,%1,%2,%3};"
        : "+f"(d[0]), "+f"(d[1]), "+f"(d[2]), "+f"(d[3])
        : "r"(A.x), "r"(A.y), "r"(A.z), "r"(A.w), "r"(B.x), "r"(B.y));
}

__global__ void build_keff_kernel(const float* __restrict__ weight,
                                  const float* __restrict__ basis) {
    const int total = SG * 4 * 50 * 128;
    int idx = blockIdx.x * blockDim.x + threadIdx.x;
    if (idx >= total) return;
    const int within = idx % 6400;
    const int gij    = idx / 6400;
    const int g  = gij / 4;
    const int ij = gij % 4;
    const int blk = within / 128;     // tap*2 + ch
    const int r   = within % 128;
    const int tap = blk >> 1;
    const int ch  = blk & 1;
    const int lane = r >> 2;
    const int j    = r & 3;
    const int grp  = lane >> 2;
    const int tig  = lane & 3;
    const int o = grp + 8 * (j & 1);
    const int c = ch * 8 + tig + 4 * (j >> 1);
    float v = 0.f;
#pragma unroll
    for (int f = 0; f < 9; ++f)
        v += weight[((o * CIN + c) * 4 + ij) * 9 + f] *
             basis[(f * SG + g) * 25 + tap];
    g_keff[idx] = tf32r(v);
}

__global__ void __launch_bounds__(256, 3)
ses_mma_kernel(const float* __restrict__ x, float* __restrict__ out) {
    extern __shared__ uint32_t dyn[];
    uint32_t* xs = dyn;                 // 2 ch-sections: [pix][tig*2+h]

    const int tid  = threadIdx.x;
    const int w    = tid >> 5;          // warp -> output rows 4w..4w+3
    const int lane = tid & 31;
    const int grp  = lane >> 2;
    const int tig  = lane & 3;

    const int bz = blockIdx.z;
    const int b  = bz / SG;
    const int g  = bz % SG;
    const int nr = g / 3;
    const int ns = g % 3;
    const int tx0 = blockIdx.x * TILE_W;
    const int ty0 = blockIdx.y * TILE_H;
    const bool interior =
        (tx0 >= 2) && (tx0 + TILE_W + 2 <= HWD) &&
        (ty0 >= 2) && (ty0 + TILE_H + 2 <= HWD);

    int ijv[4];
    int nv = 0;
#pragma unroll
    for (int ij = 0; ij < 4; ++ij)
        if (ns + (ij & 1) < 3) ijv[nv++] = ij;

    float acc[4][2][4];
#pragma unroll
    for (int r = 0; r < 4; ++r)
#pragma unroll
        for (int cr = 0; cr < 2; ++cr)
#pragma unroll
            for (int q = 0; q < 4; ++q) acc[r][cr][q] = 0.f;

    for (int sIdx = 0; sIdx < nv; ++sIdx) {
        const int ij = ijv[sIdx];
        const int sp = ((nr + (ij >> 1)) & 3) * 3 + (ns + (ij & 1));
        const uint32_t* xb = reinterpret_cast<const uint32_t*>(
            x + ((((size_t)b * CIN) * SG + sp) << 14));   // + c*(SG<<14)

        // fill: raw fp32 bits (HMMA.TF32 truncates), one uint2 (c, c+4) pair
        if (interior) {
            for (int e = tid; e < 2 * 4 * NPIX; e += 256) {
                const int tg  = e & 3;
                const int pe  = e >> 2;
                const int ch  = pe / NPIX;
                const int pix = pe - ch * NPIX;
                const int rr  = pix / HALO_W;
                const int cc  = pix - rr * HALO_W;
                const int c0 = ch * 8 + tg;
                const size_t off = (size_t)(ty0 + rr - 2) * HWD + (tx0 + cc - 2);
                const size_t pstride = (size_t)SG << 14;
                uint2 val;
                val.x = __ldg(xb + (size_t)c0 * pstride + off);
                val.y = __ldg(xb + (size_t)(c0 + 4) * pstride + off);
                *reinterpret_cast<uint2*>(xs + ch * SEC + pix * 8 + tg * 2) = val;
            }
        } else {
            for (int e = tid; e < 2 * 4 * NPIX; e += 256) {
                const int tg  = e & 3;
                const int pe  = e >> 2;
                const int ch  = pe / NPIX;
                const int pix = pe - ch * NPIX;
                const int rr  = pix / HALO_W;
                const int cc  = pix - rr * HALO_W;
                const int gy = ty0 + rr - 2;
                const int gx = tx0 + cc - 2;
                const int c0 = ch * 8 + tg;
                uint2 val = make_uint2(0u, 0u);
                if ((unsigned)gy < (unsigned)HWD && (unsigned)gx < (unsigned)HWD) {
                    const size_t off = (size_t)gy * HWD + gx;
                    const size_t pstride = (size_t)SG << 14;
                    val.x = __ldg(xb + (size_t)c0 * pstride + off);
                    val.y = __ldg(xb + (size_t)(c0 + 4) * pstride + off);
                }
                *reinterpret_cast<uint2*>(xs + ch * SEC + pix * 8 + tg * 2) = val;
            }
        }
        __syncthreads();

        // A fragments straight from global (L1/L2-resident, coalesced)
        const uint32_t* kg = g_keff + (size_t)(g * 4 + ij) * 6400 + lane * 4;

#pragma unroll
        for (int ch = 0; ch < 2; ++ch) {
            const uint32_t* kbase = kg + ch * 128;
            const uint32_t* xsec =
                xs + ch * SEC + (4 * w * HALO_W + grp) * 8 + tig * 2;

#pragma unroll
            for (int kx = 0; kx < 5; ++kx) {
                uint4 A[5];
#pragma unroll
                for (int ky = 0; ky < 5; ++ky)
                    A[ky] = __ldg(reinterpret_cast<const uint4*>(
                        kbase + (ky * 5 + kx) * 256));

                const uint32_t* pb = xsec + kx * 8;
#pragma unroll
                for (int u = 0; u < 8; ++u) {
                    const uint32_t* pu = pb + u * (HALO_W * 8);
                    uint2 Bv[2];
#pragma unroll
                    for (int cr = 0; cr < 2; ++cr)
                        Bv[cr] = *reinterpret_cast<const uint2*>(pu + cr * 64);
#pragma unroll
                    for (int ky = 0; ky < 5; ++ky) {
                        if (ky <= u && u - ky <= 3) {
                            const int r = u - ky;
#pragma unroll
                            for (int cr = 0; cr < 2; ++cr)
                                mma_tf32(acc[r][cr], A[ky], Bv[cr]);
                        }
                    }
                }
            }
        }
        __syncthreads();
    }

#pragma unroll
    for (int r = 0; r < 4; ++r) {
        const int row = ty0 + 4 * w + r;
#pragma unroll
        for (int cr = 0; cr < 2; ++cr) {
            const int px = tx0 + cr * 8 + tig * 2;
            float* o0 = out + ((((size_t)b * COUT + grp)     * SG + g) << 14) +
                        row * HWD + px;
            float* o1 = out + ((((size_t)b * COUT + grp + 8) * SG + g) << 14) +
                        row * HWD + px;
            *reinterpret_cast<float2*>(o0) =
                make_float2(acc[r][cr][0], acc[r][cr][1]);
            *reinterpret_cast<float2*>(o1) =
                make_float2(acc[r][cr][2], acc[r][cr][3]);
        }
    }
}

extern "C" void kernel_launch(void* const* d_in, const int* in_sizes, int n_in,
                              void* d_out, int out_size) {
    const float* x      = (const float*)d_in[0];
    const float* weight = (const float*)d_in[1];
    const float* basis  = (const float*)d_in[2];
    float* out = (float*)d_out;

    const int total = SG * 4 * 50 * 128;
    build_keff_kernel<<<(total + 255) / 256, 256>>>(weight, basis);

    cudaFuncSetAttribute(ses_mma_kernel,
                         cudaFuncAttributeMaxDynamicSharedMemorySize,
                         SMEM_BYTES);
    dim3 grid(HWD / TILE_W, HWD / TILE_H, BATCH * SG);
    ses_mma_kernel<<<grid, 256, SMEM_BYTES>>>(x, out);
}